// round 15
// baseline (speedup 1.0000x reference)
#include <cuda_runtime.h>
#include <cuda_fp16.h>
#include <math.h>

#define BSZ 2
#define TSEQ 4096
#define CDIM 768
#define NH 12
#define HD 64
#define MTOK (BSZ * TSEQ)      // 8192
#define NQKV (3 * CDIM)        // 2304
#define BH (BSZ * NH)          // 24

// Scratch (allocation-free rule: device globals) — all fp16
__device__ __half g_Q[(size_t)BH * TSEQ * HD];   // [b*H+h, T, D], pre-scaled
__device__ __half g_K[(size_t)BH * TSEQ * HD];
__device__ __half g_V[(size_t)BH * TSEQ * HD];
__device__ __half g_Y[(size_t)MTOK * CDIM];      // attention out, [B*T, C]
__device__ __half g_Xh[(size_t)MTOK * CDIM];     // x in fp16
__device__ __half g_Wqkvh[(size_t)CDIM * NQKV];  // Wqkv in fp16
__device__ __half g_Wprojh[(size_t)CDIM * CDIM]; // Wproj in fp16

// ---------------------------------------------------------------------------
// helpers
// ---------------------------------------------------------------------------
__device__ __forceinline__ void mma16(float* c, const unsigned* a, unsigned b0, unsigned b1) {
    asm volatile(
        "mma.sync.aligned.m16n8k16.row.col.f32.f16.f16.f32 "
        "{%0,%1,%2,%3}, {%4,%5,%6,%7}, {%8,%9}, {%0,%1,%2,%3};"
        : "+f"(c[0]), "+f"(c[1]), "+f"(c[2]), "+f"(c[3])
        : "r"(a[0]), "r"(a[1]), "r"(a[2]), "r"(a[3]), "r"(b0), "r"(b1));
}
__device__ __forceinline__ void ldsm4(unsigned addr, unsigned& r0, unsigned& r1,
                                      unsigned& r2, unsigned& r3) {
    asm volatile("ldmatrix.sync.aligned.m8n8.x4.shared.b16 {%0,%1,%2,%3}, [%4];"
                 : "=r"(r0), "=r"(r1), "=r"(r2), "=r"(r3) : "r"(addr));
}
__device__ __forceinline__ void ldsm4t(unsigned addr, unsigned& r0, unsigned& r1,
                                       unsigned& r2, unsigned& r3) {
    asm volatile("ldmatrix.sync.aligned.m8n8.x4.trans.shared.b16 {%0,%1,%2,%3}, [%4];"
                 : "=r"(r0), "=r"(r1), "=r"(r2), "=r"(r3) : "r"(addr));
}
__device__ __forceinline__ float ex2(float x) {
    float r;
    asm("ex2.approx.f32 %0, %1;" : "=f"(r) : "f"(x));
    return r;
}
__device__ __forceinline__ unsigned packh2(float a, float b) {
    __half2 h = __floats2half2_rn(a, b);
    return *(unsigned*)&h;
}
__device__ __forceinline__ uint4 cvt8(const float* p) {
    float4 f0 = *(const float4*)p;
    float4 f1 = *(const float4*)(p + 4);
    uint4 u;
    u.x = packh2(f0.x, f0.y); u.y = packh2(f0.z, f0.w);
    u.z = packh2(f1.x, f1.y); u.w = packh2(f1.z, f1.w);
    return u;
}
__device__ __forceinline__ void cpa16(unsigned dst, const void* src) {
    asm volatile("cp.async.cg.shared.global [%0], [%1], 16;" :: "r"(dst), "l"(src));
}
#define CPCOMMIT() asm volatile("cp.async.commit_group;")
#define CPWAIT0()  asm volatile("cp.async.wait_group 0;")
#define CPWAIT1()  asm volatile("cp.async.wait_group 1;")
#define CPWAIT2()  asm volatile("cp.async.wait_group 2;")

#define QS (0.125f * 1.4426950408889634f)   // 1/sqrt(D) * log2(e)

// ---------------------------------------------------------------------------
// Kernel 0: fused fp32 -> fp16 convert for x, Wqkv, Wproj (one launch)
// ---------------------------------------------------------------------------
#define NX (MTOK * CDIM)        // 6291456
#define NW (CDIM * NQKV)        // 1769472
#define NP (CDIM * CDIM)        // 589824
#define NTOT (NX + NW + NP)     // 8650752 (divisible by 8)

__global__ __launch_bounds__(256) void f2h_all(const float* __restrict__ x,
                                               const float* __restrict__ wq,
                                               const float* __restrict__ wp)
{
    const int i = ((int)blockIdx.x * 256 + (int)threadIdx.x) * 8;
    if (i < NX) {
        *(uint4*)(g_Xh + i) = cvt8(x + i);
    } else if (i < NX + NW) {
        const int j = i - NX;
        *(uint4*)(g_Wqkvh + j) = cvt8(wq + j);
    } else if (i < NTOT) {
        const int j = i - NX - NW;
        *(uint4*)(g_Wprojh + j) = cvt8(wp + j);
    }
}

// ---------------------------------------------------------------------------
// GEMM (fp16 mma + ldmatrix + 3-stage cp.async, single sync/iter, 2 CTAs/SM)
// 128x128x64 tile, 256 threads (8 warps, warp tile 64x32).
// ---------------------------------------------------------------------------
#define ASTR 72
#define BSTR 136
#define STAGEH (128 * ASTR + 64 * BSTR)   // halves per stage (17920)
#define NSTAGE 3
#define GEMM_SMEM (NSTAGE * STAGEH * 2)   // 107520 bytes

__device__ __forceinline__ void scatter_qkv2(int m, int n, float v0, float v1) {
    const int b = m >> 12;
    const int tt = m & 4095;
    const int sel = n / CDIM;            // 0=Q,1=K,2=V
    const int r = n - sel * CDIM;
    const int h = r >> 6;
    const int d = r & 63;
    if (sel == 0) { v0 *= QS; v1 *= QS; }
    __half* dst = (sel == 0) ? g_Q : ((sel == 1) ? g_K : g_V);
    *(__half2*)&dst[((size_t)(b * NH + h) * TSEQ + tt) * HD + d] = __floats2half2_rn(v0, v1);
}

template <bool IS_QKV>
__device__ __forceinline__ void gemm_f16_body(const __half* __restrict__ Ag,
                                              const __half* __restrict__ Bg,
                                              const float* __restrict__ bias,
                                              float* __restrict__ out, int ldb)
{
    extern __shared__ __half dsm[];
    const unsigned smb = (unsigned)__cvta_generic_to_shared(dsm);

    const int tid = (int)threadIdx.x;
    const int lane = tid & 31;
    const int wid = tid >> 5;
    const int g = lane >> 2;
    const int t = lane & 3;
    const int m0 = blockIdx.y * 128;
    const int n0 = blockIdx.x * 128;
    const int m0w = (wid & 1) * 64;
    const int n0w = (wid >> 1) * 32;

    float acc[4][4][4];
#pragma unroll
    for (int i = 0; i < 4; i++)
#pragma unroll
        for (int j = 0; j < 4; j++)
#pragma unroll
            for (int k = 0; k < 4; k++) acc[i][j][k] = 0.f;

    const int ar = tid >> 1, ac = (tid & 1) * 32;
    const int br = tid >> 2, bc = (tid & 3) * 32;
    const int arow = lane & 15;
    const int koff = (lane & 16) ? 8 : 0;
    const int trow = (lane & 7) + ((lane >> 3) & 3) * 8;

    const int NIT = CDIM / 64;   // 12

    auto prefetch = [&](int it, int s) {
        const int kb = it * 64;
        const unsigned abase = smb + (unsigned)(s * STAGEH) * 2u;
        const unsigned bbase = abase + (unsigned)(128 * ASTR) * 2u;
        const __half* asrc = Ag + (size_t)(m0 + ar) * CDIM + kb + ac;
        const unsigned adst = abase + (unsigned)(ar * ASTR + ac) * 2u;
#pragma unroll
        for (int v = 0; v < 4; v++) cpa16(adst + v * 16u, asrc + v * 8);
        const __half* bsrc = Bg + (size_t)(kb + br) * ldb + n0 + bc;
        const unsigned bdst = bbase + (unsigned)(br * BSTR + bc) * 2u;
#pragma unroll
        for (int v = 0; v < 4; v++) cpa16(bdst + v * 16u, bsrc + v * 8);
    };

    prefetch(0, 0); CPCOMMIT();
    prefetch(1, 1); CPCOMMIT();

    int s = 0;
    int ps = 2;
    for (int it = 0; it < NIT; it++) {
        CPWAIT1();
        __syncthreads();
        if (it + 2 < NIT) prefetch(it + 2, ps);
        CPCOMMIT();

        const unsigned asb = smb + (unsigned)(s * STAGEH) * 2u;
        const unsigned bsb = asb + (unsigned)(128 * ASTR) * 2u;

#pragma unroll
        for (int kc = 0; kc < 2; kc++) {
            unsigned bb[4][4];
#pragma unroll
            for (int nf = 0; nf < 4; nf++)
                ldsm4t(bsb + (unsigned)((kc * 32 + trow) * BSTR + n0w + nf * 8) * 2u,
                       bb[nf][0], bb[nf][1], bb[nf][2], bb[nf][3]);
#pragma unroll
            for (int mf = 0; mf < 4; mf++) {
                unsigned a0[4], a1[4];
                const unsigned base = asb +
                    (unsigned)((m0w + mf * 16 + arow) * ASTR + kc * 32 + koff) * 2u;
                ldsm4(base,      a0[0], a0[1], a0[2], a0[3]);
                ldsm4(base + 32, a1[0], a1[1], a1[2], a1[3]);
#pragma unroll
                for (int nf = 0; nf < 4; nf++) {
                    mma16(acc[mf][nf], a0, bb[nf][0], bb[nf][1]);
                    mma16(acc[mf][nf], a1, bb[nf][2], bb[nf][3]);
                }
            }
        }
        s = (s == 2) ? 0 : s + 1;
        ps = (ps == 2) ? 0 : ps + 1;
    }

#pragma unroll
    for (int mf = 0; mf < 4; mf++) {
        const int r0 = m0 + m0w + mf * 16 + g;
#pragma unroll
        for (int nf = 0; nf < 4; nf++) {
            const int c0 = n0 + n0w + nf * 8 + 2 * t;
            const float b0 = bias[c0], b1 = bias[c0 + 1];
            if (IS_QKV) {
                scatter_qkv2(r0,     c0, acc[mf][nf][0] + b0, acc[mf][nf][1] + b1);
                scatter_qkv2(r0 + 8, c0, acc[mf][nf][2] + b0, acc[mf][nf][3] + b1);
            } else {
                *(float2*)&out[(size_t)r0 * CDIM + c0] =
                    make_float2(acc[mf][nf][0] + b0, acc[mf][nf][1] + b1);
                *(float2*)&out[(size_t)(r0 + 8) * CDIM + c0] =
                    make_float2(acc[mf][nf][2] + b0, acc[mf][nf][3] + b1);
            }
        }
    }
}

__global__ __launch_bounds__(256, 2) void qkv_gemm_f16(const float* __restrict__ bias)
{
    gemm_f16_body<true>(g_Xh, g_Wqkvh, bias, nullptr, NQKV);
}

__global__ __launch_bounds__(256, 2) void proj_gemm_f16(const float* __restrict__ bias,
                                                        float* __restrict__ out)
{
    gemm_f16_body<false>(g_Y, g_Wprojh, bias, out, CDIM);
}

// ---------------------------------------------------------------------------
// Kernel 2: causal flash attention, fp16 mma, 4-stage cp.async K/V ring,
// single sync per tile. Block = 128 q x 64 kv, 8 warps.  [R9 winner]
// ---------------------------------------------------------------------------
#define KVSTR 72
#define KVBUF (64 * KVSTR)             // halves per K or V buffer (4608)
#define KVSTAGE 4
#define ATT_SMEM (KVSTAGE * 2 * KVBUF * 2)   // 73728 bytes

__global__ __launch_bounds__(256, 2) void attn_fa16()
{
    extern __shared__ __half sm[];
    const unsigned smb = (unsigned)__cvta_generic_to_shared(sm);

    const int qt  = (int)gridDim.x - 1 - (int)blockIdx.x;
    const int bh  = (int)blockIdx.y;
    const int tid = (int)threadIdx.x;
    const int lane = tid & 31;
    const int wid  = tid >> 5;
    const int g = lane >> 2;
    const int t = lane & 3;

    const __half* Qg = g_Q + (size_t)bh * TSEQ * HD + (size_t)qt * 128 * HD;
    const __half* Kg = g_K + (size_t)bh * TSEQ * HD;
    const __half* Vg = g_V + (size_t)bh * TSEQ * HD;

    // ---- stage Q into stage-0 region (consumed before ring starts)
    {
        const int r = tid >> 1;
        const int c0 = (tid & 1) * 32;
        const __half* src = Qg + r * 64 + c0;
        const unsigned dst = smb + (unsigned)(r * KVSTR + c0) * 2u;
#pragma unroll
        for (int v = 0; v < 4; v++) cpa16(dst + v * 16u, src + v * 8);
        CPCOMMIT();
        CPWAIT0();
    }
    __syncthreads();

    unsigned qf[4][4];
    {
        const int qrow = wid * 16 + (lane & 15);
        const int koff = (lane & 16) ? 8 : 0;
#pragma unroll
        for (int ks = 0; ks < 4; ks++)
            ldsm4(smb + (unsigned)(qrow * KVSTR + ks * 16 + koff) * 2u,
                  qf[ks][0], qf[ks][1], qf[ks][2], qf[ks][3]);
    }
    __syncthreads();

    float of[8][4];
#pragma unroll
    for (int i = 0; i < 8; i++)
#pragma unroll
        for (int j = 0; j < 4; j++) of[i][j] = 0.f;
    float m0 = -1e30f, m1 = -1e30f, l0 = 0.f, l1 = 0.f;

    const int r0 = qt * 128 + wid * 16 + g;
    const int r1 = r0 + 8;
    const int ntiles = 2 * qt + 2;

    const int kvr = tid >> 2;
    const int kvc = (tid & 3) * 16;
    auto prefetch_kv = [&](int jt, int s) {
        const unsigned kdst = smb + (unsigned)(s * 2 * KVBUF + kvr * KVSTR + kvc) * 2u;
        const unsigned vdst = kdst + (unsigned)KVBUF * 2u;
        const __half* ks = Kg + (size_t)(jt * 64 + kvr) * 64 + kvc;
        const __half* vs = Vg + (size_t)(jt * 64 + kvr) * 64 + kvc;
        cpa16(kdst,       ks);
        cpa16(kdst + 16u, ks + 8);
        cpa16(vdst,       vs);
        cpa16(vdst + 16u, vs + 8);
    };

    // prologue: 3 tiles in flight (empty commits if fewer tiles)
    prefetch_kv(0, 0); CPCOMMIT();
    if (1 < ntiles) prefetch_kv(1, 1);
    CPCOMMIT();
    if (2 < ntiles) prefetch_kv(2, 2);
    CPCOMMIT();

    for (int jt = 0; jt < ntiles; jt++) {
        CPWAIT2();
        __syncthreads();
        if (jt + 3 < ntiles) prefetch_kv(jt + 3, (jt + 3) & 3);
        CPCOMMIT();

        const int s = jt & 3;
        const unsigned kb = smb + (unsigned)(s * 2 * KVBUF) * 2u;
        const unsigned vb = kb + (unsigned)KVBUF * 2u;

        float sa[8][4];
#pragma unroll
        for (int i = 0; i < 8; i++)
#pragma unroll
            for (int j = 0; j < 4; j++) sa[i][j] = 0.f;

        {
            const int nrow = (lane & 7);
            const int kc = ((lane >> 3) & 3) * 8;
#pragma unroll
            for (int nf = 0; nf < 8; nf++) {
                unsigned b0, b1, b2, b3;
                ldsm4(kb + (unsigned)((nf * 8 + nrow) * KVSTR + kc) * 2u, b0, b1, b2, b3);
                mma16(sa[nf], qf[0], b0, b1);
                mma16(sa[nf], qf[1], b2, b3);
                ldsm4(kb + (unsigned)((nf * 8 + nrow) * KVSTR + 32 + kc) * 2u, b0, b1, b2, b3);
                mma16(sa[nf], qf[2], b0, b1);
                mma16(sa[nf], qf[3], b2, b3);
            }
        }

        if (jt * 64 + 63 > qt * 128 + wid * 16) {
#pragma unroll
            for (int nf = 0; nf < 8; nf++) {
                const int c = jt * 64 + nf * 8 + 2 * t;
                if (c > r0)     sa[nf][0] = -1e30f;
                if (c + 1 > r0) sa[nf][1] = -1e30f;
                if (c > r1)     sa[nf][2] = -1e30f;
                if (c + 1 > r1) sa[nf][3] = -1e30f;
            }
        }

        float mx0 = -1e30f, mx1 = -1e30f;
#pragma unroll
        for (int nf = 0; nf < 8; nf++) {
            mx0 = fmaxf(mx0, fmaxf(sa[nf][0], sa[nf][1]));
            mx1 = fmaxf(mx1, fmaxf(sa[nf][2], sa[nf][3]));
        }
        mx0 = fmaxf(mx0, __shfl_xor_sync(0xffffffffu, mx0, 1));
        mx0 = fmaxf(mx0, __shfl_xor_sync(0xffffffffu, mx0, 2));
        mx1 = fmaxf(mx1, __shfl_xor_sync(0xffffffffu, mx1, 1));
        mx1 = fmaxf(mx1, __shfl_xor_sync(0xffffffffu, mx1, 2));

        const float nm0 = fmaxf(m0, mx0);
        const float nm1 = fmaxf(m1, mx1);
        const float cr0 = ex2(m0 - nm0);
        const float cr1 = ex2(m1 - nm1);
        m0 = nm0; m1 = nm1;

        float ls0 = 0.f, ls1 = 0.f;
#pragma unroll
        for (int nf = 0; nf < 8; nf++) {
            sa[nf][0] = ex2(sa[nf][0] - nm0);
            sa[nf][1] = ex2(sa[nf][1] - nm0);
            sa[nf][2] = ex2(sa[nf][2] - nm1);
            sa[nf][3] = ex2(sa[nf][3] - nm1);
            ls0 += sa[nf][0] + sa[nf][1];
            ls1 += sa[nf][2] + sa[nf][3];
        }
        ls0 += __shfl_xor_sync(0xffffffffu, ls0, 1);
        ls0 += __shfl_xor_sync(0xffffffffu, ls0, 2);
        ls1 += __shfl_xor_sync(0xffffffffu, ls1, 1);
        ls1 += __shfl_xor_sync(0xffffffffu, ls1, 2);
        l0 = l0 * cr0 + ls0;
        l1 = l1 * cr1 + ls1;

#pragma unroll
        for (int df = 0; df < 8; df++) {
            of[df][0] *= cr0; of[df][1] *= cr0;
            of[df][2] *= cr1; of[df][3] *= cr1;
        }

        unsigned pf[4][4];
#pragma unroll
        for (int kc = 0; kc < 4; kc++) {
            pf[kc][0] = packh2(sa[2 * kc][0],     sa[2 * kc][1]);
            pf[kc][1] = packh2(sa[2 * kc][2],     sa[2 * kc][3]);
            pf[kc][2] = packh2(sa[2 * kc + 1][0], sa[2 * kc + 1][1]);
            pf[kc][3] = packh2(sa[2 * kc + 1][2], sa[2 * kc + 1][3]);
        }

        {
            const int vrow = (lane & 7) + ((lane >> 3) & 3) * 8;
#pragma unroll
            for (int df = 0; df < 8; df++) {
                unsigned b0, b1, b2, b3;
                ldsm4t(vb + (unsigned)(vrow * KVSTR + df * 8) * 2u, b0, b1, b2, b3);
                mma16(of[df], pf[0], b0, b1);
                mma16(of[df], pf[1], b2, b3);
                ldsm4t(vb + (unsigned)((vrow + 32) * KVSTR + df * 8) * 2u, b0, b1, b2, b3);
                mma16(of[df], pf[2], b0, b1);
                mma16(of[df], pf[3], b2, b3);
            }
        }
    }

    const int b = bh / NH;
    const int h = bh % NH;
    const float il0 = 1.f / l0;
    const float il1 = 1.f / l1;
#pragma unroll
    for (int df = 0; df < 8; df++) {
        const int col = h * 64 + df * 8 + 2 * t;
        *(__half2*)&g_Y[(size_t)(b * TSEQ + r0) * CDIM + col] =
            __floats2half2_rn(of[df][0] * il0, of[df][1] * il0);
        *(__half2*)&g_Y[(size_t)(b * TSEQ + r1) * CDIM + col] =
            __floats2half2_rn(of[df][2] * il1, of[df][3] * il1);
    }
}

// ---------------------------------------------------------------------------
extern "C" void kernel_launch(void* const* d_in, const int* in_sizes, int n_in,
                              void* d_out, int out_size)
{
    const float* x     = (const float*)d_in[0];
    const float* Wqkv  = (const float*)d_in[1];
    const float* bqkv  = (const float*)d_in[2];
    const float* Wproj = (const float*)d_in[3];
    const float* bproj = (const float*)d_in[4];
    float* out = (float*)d_out;

    cudaFuncSetAttribute(qkv_gemm_f16, cudaFuncAttributeMaxDynamicSharedMemorySize, GEMM_SMEM);
    cudaFuncSetAttribute(proj_gemm_f16, cudaFuncAttributeMaxDynamicSharedMemorySize, GEMM_SMEM);
    cudaFuncSetAttribute(attn_fa16, cudaFuncAttributeMaxDynamicSharedMemorySize, ATT_SMEM);

    f2h_all<<<NTOT / 2048, 256>>>(x, Wqkv, Wproj);
    qkv_gemm_f16<<<dim3(NQKV / 128, MTOK / 128), 256, GEMM_SMEM>>>(bqkv);
    attn_fa16<<<dim3(TSEQ / 128, BH), 256, ATT_SMEM>>>();
    proj_gemm_f16<<<dim3(CDIM / 128, MTOK / 128), 256, GEMM_SMEM>>>(bproj, out);
}

// round 16
// speedup vs baseline: 1.0031x; 1.0031x over previous
#include <cuda_runtime.h>
#include <cuda_fp16.h>
#include <math.h>

#define BSZ 2
#define TSEQ 4096
#define CDIM 768
#define NH 12
#define HD 64
#define MTOK (BSZ * TSEQ)      // 8192
#define NQKV (3 * CDIM)        // 2304
#define BH (BSZ * NH)          // 24

// Scratch (allocation-free rule: device globals) — all fp16
__device__ __half g_Q[(size_t)BH * TSEQ * HD];   // [b*H+h, T, D], pre-scaled
__device__ __half g_K[(size_t)BH * TSEQ * HD];
__device__ __half g_V[(size_t)BH * TSEQ * HD];
__device__ __half g_Y[(size_t)MTOK * CDIM];      // attention out, [B*T, C]
__device__ __half g_Xh[(size_t)MTOK * CDIM];     // x in fp16
__device__ __half g_Wqkvh[(size_t)CDIM * NQKV];  // Wqkv in fp16
__device__ __half g_Wprojh[(size_t)CDIM * CDIM]; // Wproj in fp16

// ---------------------------------------------------------------------------
// helpers
// ---------------------------------------------------------------------------
__device__ __forceinline__ void mma16(float* c, const unsigned* a, unsigned b0, unsigned b1) {
    asm volatile(
        "mma.sync.aligned.m16n8k16.row.col.f32.f16.f16.f32 "
        "{%0,%1,%2,%3}, {%4,%5,%6,%7}, {%8,%9}, {%0,%1,%2,%3};"
        : "+f"(c[0]), "+f"(c[1]), "+f"(c[2]), "+f"(c[3])
        : "r"(a[0]), "r"(a[1]), "r"(a[2]), "r"(a[3]), "r"(b0), "r"(b1));
}
__device__ __forceinline__ void ldsm4(unsigned addr, unsigned& r0, unsigned& r1,
                                      unsigned& r2, unsigned& r3) {
    asm volatile("ldmatrix.sync.aligned.m8n8.x4.shared.b16 {%0,%1,%2,%3}, [%4];"
                 : "=r"(r0), "=r"(r1), "=r"(r2), "=r"(r3) : "r"(addr));
}
__device__ __forceinline__ void ldsm4t(unsigned addr, unsigned& r0, unsigned& r1,
                                       unsigned& r2, unsigned& r3) {
    asm volatile("ldmatrix.sync.aligned.m8n8.x4.trans.shared.b16 {%0,%1,%2,%3}, [%4];"
                 : "=r"(r0), "=r"(r1), "=r"(r2), "=r"(r3) : "r"(addr));
}
__device__ __forceinline__ float ex2(float x) {
    float r;
    asm("ex2.approx.f32 %0, %1;" : "=f"(r) : "f"(x));
    return r;
}
__device__ __forceinline__ unsigned packh2(float a, float b) {
    __half2 h = __floats2half2_rn(a, b);
    return *(unsigned*)&h;
}
__device__ __forceinline__ uint4 cvt8(const float* p) {
    float4 f0 = *(const float4*)p;
    float4 f1 = *(const float4*)(p + 4);
    uint4 u;
    u.x = packh2(f0.x, f0.y); u.y = packh2(f0.z, f0.w);
    u.z = packh2(f1.x, f1.y); u.w = packh2(f1.z, f1.w);
    return u;
}
__device__ __forceinline__ void cpa16(unsigned dst, const void* src) {
    asm volatile("cp.async.cg.shared.global [%0], [%1], 16;" :: "r"(dst), "l"(src));
}
#define CPCOMMIT() asm volatile("cp.async.commit_group;")
#define CPWAIT0()  asm volatile("cp.async.wait_group 0;")
#define CPWAIT1()  asm volatile("cp.async.wait_group 1;")
#define CPWAIT2()  asm volatile("cp.async.wait_group 2;")

#define QS (0.125f * 1.4426950408889634f)   // 1/sqrt(D) * log2(e)

// ---------------------------------------------------------------------------
// Kernel 0: fused fp32 -> fp16 convert for x, Wqkv, Wproj (one launch)
// ---------------------------------------------------------------------------
#define NX (MTOK * CDIM)        // 6291456
#define NW (CDIM * NQKV)        // 1769472
#define NP (CDIM * CDIM)        // 589824
#define NTOT (NX + NW + NP)     // 8650752 (divisible by 8)

__global__ __launch_bounds__(256) void f2h_all(const float* __restrict__ x,
                                               const float* __restrict__ wq,
                                               const float* __restrict__ wp)
{
    const int i = ((int)blockIdx.x * 256 + (int)threadIdx.x) * 8;
    if (i < NX) {
        *(uint4*)(g_Xh + i) = cvt8(x + i);
    } else if (i < NX + NW) {
        const int j = i - NX;
        *(uint4*)(g_Wqkvh + j) = cvt8(wq + j);
    } else if (i < NTOT) {
        const int j = i - NX - NW;
        *(uint4*)(g_Wprojh + j) = cvt8(wp + j);
    }
}

// ---------------------------------------------------------------------------
// GEMM (fp16 mma + ldmatrix + 3-stage cp.async, single sync/iter, 2 CTAs/SM)
// 128x128x64 tile, 256 threads (8 warps, warp tile 64x32).
// ---------------------------------------------------------------------------
#define ASTR 72
#define BSTR 136
#define STAGEH (128 * ASTR + 64 * BSTR)   // halves per stage (17920)
#define NSTAGE 3
#define GEMM_SMEM (NSTAGE * STAGEH * 2)   // 107520 bytes

__device__ __forceinline__ void scatter_qkv2(int m, int n, float v0, float v1) {
    const int b = m >> 12;
    const int tt = m & 4095;
    const int sel = n / CDIM;            // 0=Q,1=K,2=V
    const int r = n - sel * CDIM;
    const int h = r >> 6;
    const int d = r & 63;
    if (sel == 0) { v0 *= QS; v1 *= QS; }
    __half* dst = (sel == 0) ? g_Q : ((sel == 1) ? g_K : g_V);
    *(__half2*)&dst[((size_t)(b * NH + h) * TSEQ + tt) * HD + d] = __floats2half2_rn(v0, v1);
}

template <bool IS_QKV>
__device__ __forceinline__ void gemm_f16_body(const __half* __restrict__ Ag,
                                              const __half* __restrict__ Bg,
                                              const float* __restrict__ bias,
                                              float* __restrict__ out, int ldb)
{
    extern __shared__ __half dsm[];
    const unsigned smb = (unsigned)__cvta_generic_to_shared(dsm);

    const int tid = (int)threadIdx.x;
    const int lane = tid & 31;
    const int wid = tid >> 5;
    const int g = lane >> 2;
    const int t = lane & 3;
    const int m0 = blockIdx.y * 128;
    const int n0 = blockIdx.x * 128;
    const int m0w = (wid & 1) * 64;
    const int n0w = (wid >> 1) * 32;

    float acc[4][4][4];
#pragma unroll
    for (int i = 0; i < 4; i++)
#pragma unroll
        for (int j = 0; j < 4; j++)
#pragma unroll
            for (int k = 0; k < 4; k++) acc[i][j][k] = 0.f;

    const int ar = tid >> 1, ac = (tid & 1) * 32;
    const int br = tid >> 2, bc = (tid & 3) * 32;
    const int arow = lane & 15;
    const int koff = (lane & 16) ? 8 : 0;
    const int trow = (lane & 7) + ((lane >> 3) & 3) * 8;

    const int NIT = CDIM / 64;   // 12

    auto prefetch = [&](int it, int s) {
        const int kb = it * 64;
        const unsigned abase = smb + (unsigned)(s * STAGEH) * 2u;
        const unsigned bbase = abase + (unsigned)(128 * ASTR) * 2u;
        const __half* asrc = Ag + (size_t)(m0 + ar) * CDIM + kb + ac;
        const unsigned adst = abase + (unsigned)(ar * ASTR + ac) * 2u;
#pragma unroll
        for (int v = 0; v < 4; v++) cpa16(adst + v * 16u, asrc + v * 8);
        const __half* bsrc = Bg + (size_t)(kb + br) * ldb + n0 + bc;
        const unsigned bdst = bbase + (unsigned)(br * BSTR + bc) * 2u;
#pragma unroll
        for (int v = 0; v < 4; v++) cpa16(bdst + v * 16u, bsrc + v * 8);
    };

    prefetch(0, 0); CPCOMMIT();
    prefetch(1, 1); CPCOMMIT();

    int s = 0;
    int ps = 2;
    for (int it = 0; it < NIT; it++) {
        CPWAIT1();
        __syncthreads();
        if (it + 2 < NIT) prefetch(it + 2, ps);
        CPCOMMIT();

        const unsigned asb = smb + (unsigned)(s * STAGEH) * 2u;
        const unsigned bsb = asb + (unsigned)(128 * ASTR) * 2u;

#pragma unroll
        for (int kc = 0; kc < 2; kc++) {
            unsigned bb[4][4];
#pragma unroll
            for (int nf = 0; nf < 4; nf++)
                ldsm4t(bsb + (unsigned)((kc * 32 + trow) * BSTR + n0w + nf * 8) * 2u,
                       bb[nf][0], bb[nf][1], bb[nf][2], bb[nf][3]);
#pragma unroll
            for (int mf = 0; mf < 4; mf++) {
                unsigned a0[4], a1[4];
                const unsigned base = asb +
                    (unsigned)((m0w + mf * 16 + arow) * ASTR + kc * 32 + koff) * 2u;
                ldsm4(base,      a0[0], a0[1], a0[2], a0[3]);
                ldsm4(base + 32, a1[0], a1[1], a1[2], a1[3]);
#pragma unroll
                for (int nf = 0; nf < 4; nf++) {
                    mma16(acc[mf][nf], a0, bb[nf][0], bb[nf][1]);
                    mma16(acc[mf][nf], a1, bb[nf][2], bb[nf][3]);
                }
            }
        }
        s = (s == 2) ? 0 : s + 1;
        ps = (ps == 2) ? 0 : ps + 1;
    }

#pragma unroll
    for (int mf = 0; mf < 4; mf++) {
        const int r0 = m0 + m0w + mf * 16 + g;
#pragma unroll
        for (int nf = 0; nf < 4; nf++) {
            const int c0 = n0 + n0w + nf * 8 + 2 * t;
            const float b0 = bias[c0], b1 = bias[c0 + 1];
            if (IS_QKV) {
                scatter_qkv2(r0,     c0, acc[mf][nf][0] + b0, acc[mf][nf][1] + b1);
                scatter_qkv2(r0 + 8, c0, acc[mf][nf][2] + b0, acc[mf][nf][3] + b1);
            } else {
                *(float2*)&out[(size_t)r0 * CDIM + c0] =
                    make_float2(acc[mf][nf][0] + b0, acc[mf][nf][1] + b1);
                *(float2*)&out[(size_t)(r0 + 8) * CDIM + c0] =
                    make_float2(acc[mf][nf][2] + b0, acc[mf][nf][3] + b1);
            }
        }
    }
}

__global__ __launch_bounds__(256, 2) void qkv_gemm_f16(const float* __restrict__ bias)
{
    gemm_f16_body<true>(g_Xh, g_Wqkvh, bias, nullptr, NQKV);
}

__global__ __launch_bounds__(256, 2) void proj_gemm_f16(const float* __restrict__ bias,
                                                        float* __restrict__ out)
{
    gemm_f16_body<false>(g_Y, g_Wprojh, bias, out, CDIM);
}

// ---------------------------------------------------------------------------
// Kernel 2: causal flash attention, fp16 mma, 4-stage cp.async K/V ring,
// single sync per tile. Block = 128 q x 64 kv, 8 warps.  [R9 winner]
// ---------------------------------------------------------------------------
#define KVSTR 72
#define KVBUF (64 * KVSTR)             // halves per K or V buffer (4608)
#define KVSTAGE 4
#define ATT_SMEM (KVSTAGE * 2 * KVBUF * 2)   // 73728 bytes

__global__ __launch_bounds__(256, 2) void attn_fa16()
{
    extern __shared__ __half sm[];
    const unsigned smb = (unsigned)__cvta_generic_to_shared(sm);

    const int qt  = (int)gridDim.x - 1 - (int)blockIdx.x;
    const int bh  = (int)blockIdx.y;
    const int tid = (int)threadIdx.x;
    const int lane = tid & 31;
    const int wid  = tid >> 5;
    const int g = lane >> 2;
    const int t = lane & 3;

    const __half* Qg = g_Q + (size_t)bh * TSEQ * HD + (size_t)qt * 128 * HD;
    const __half* Kg = g_K + (size_t)bh * TSEQ * HD;
    const __half* Vg = g_V + (size_t)bh * TSEQ * HD;

    // ---- stage Q into stage-0 region (consumed before ring starts)
    {
        const int r = tid >> 1;
        const int c0 = (tid & 1) * 32;
        const __half* src = Qg + r * 64 + c0;
        const unsigned dst = smb + (unsigned)(r * KVSTR + c0) * 2u;
#pragma unroll
        for (int v = 0; v < 4; v++) cpa16(dst + v * 16u, src + v * 8);
        CPCOMMIT();
        CPWAIT0();
    }
    __syncthreads();

    unsigned qf[4][4];
    {
        const int qrow = wid * 16 + (lane & 15);
        const int koff = (lane & 16) ? 8 : 0;
#pragma unroll
        for (int ks = 0; ks < 4; ks++)
            ldsm4(smb + (unsigned)(qrow * KVSTR + ks * 16 + koff) * 2u,
                  qf[ks][0], qf[ks][1], qf[ks][2], qf[ks][3]);
    }
    __syncthreads();

    float of[8][4];
#pragma unroll
    for (int i = 0; i < 8; i++)
#pragma unroll
        for (int j = 0; j < 4; j++) of[i][j] = 0.f;
    float m0 = -1e30f, m1 = -1e30f, l0 = 0.f, l1 = 0.f;

    const int r0 = qt * 128 + wid * 16 + g;
    const int r1 = r0 + 8;
    const int ntiles = 2 * qt + 2;

    const int kvr = tid >> 2;
    const int kvc = (tid & 3) * 16;
    auto prefetch_kv = [&](int jt, int s) {
        const unsigned kdst = smb + (unsigned)(s * 2 * KVBUF + kvr * KVSTR + kvc) * 2u;
        const unsigned vdst = kdst + (unsigned)KVBUF * 2u;
        const __half* ks = Kg + (size_t)(jt * 64 + kvr) * 64 + kvc;
        const __half* vs = Vg + (size_t)(jt * 64 + kvr) * 64 + kvc;
        cpa16(kdst,       ks);
        cpa16(kdst + 16u, ks + 8);
        cpa16(vdst,       vs);
        cpa16(vdst + 16u, vs + 8);
    };

    // prologue: 3 tiles in flight (empty commits if fewer tiles)
    prefetch_kv(0, 0); CPCOMMIT();
    if (1 < ntiles) prefetch_kv(1, 1);
    CPCOMMIT();
    if (2 < ntiles) prefetch_kv(2, 2);
    CPCOMMIT();

    for (int jt = 0; jt < ntiles; jt++) {
        CPWAIT2();
        __syncthreads();
        if (jt + 3 < ntiles) prefetch_kv(jt + 3, (jt + 3) & 3);
        CPCOMMIT();

        const int s = jt & 3;
        const unsigned kb = smb + (unsigned)(s * 2 * KVBUF) * 2u;
        const unsigned vb = kb + (unsigned)KVBUF * 2u;

        float sa[8][4];
#pragma unroll
        for (int i = 0; i < 8; i++)
#pragma unroll
            for (int j = 0; j < 4; j++) sa[i][j] = 0.f;

        {
            const int nrow = (lane & 7);
            const int kc = ((lane >> 3) & 3) * 8;
#pragma unroll
            for (int nf = 0; nf < 8; nf++) {
                unsigned b0, b1, b2, b3;
                ldsm4(kb + (unsigned)((nf * 8 + nrow) * KVSTR + kc) * 2u, b0, b1, b2, b3);
                mma16(sa[nf], qf[0], b0, b1);
                mma16(sa[nf], qf[1], b2, b3);
                ldsm4(kb + (unsigned)((nf * 8 + nrow) * KVSTR + 32 + kc) * 2u, b0, b1, b2, b3);
                mma16(sa[nf], qf[2], b0, b1);
                mma16(sa[nf], qf[3], b2, b3);
            }
        }

        if (jt * 64 + 63 > qt * 128 + wid * 16) {
#pragma unroll
            for (int nf = 0; nf < 8; nf++) {
                const int c = jt * 64 + nf * 8 + 2 * t;
                if (c > r0)     sa[nf][0] = -1e30f;
                if (c + 1 > r0) sa[nf][1] = -1e30f;
                if (c > r1)     sa[nf][2] = -1e30f;
                if (c + 1 > r1) sa[nf][3] = -1e30f;
            }
        }

        float mx0 = -1e30f, mx1 = -1e30f;
#pragma unroll
        for (int nf = 0; nf < 8; nf++) {
            mx0 = fmaxf(mx0, fmaxf(sa[nf][0], sa[nf][1]));
            mx1 = fmaxf(mx1, fmaxf(sa[nf][2], sa[nf][3]));
        }
        mx0 = fmaxf(mx0, __shfl_xor_sync(0xffffffffu, mx0, 1));
        mx0 = fmaxf(mx0, __shfl_xor_sync(0xffffffffu, mx0, 2));
        mx1 = fmaxf(mx1, __shfl_xor_sync(0xffffffffu, mx1, 1));
        mx1 = fmaxf(mx1, __shfl_xor_sync(0xffffffffu, mx1, 2));

        const float nm0 = fmaxf(m0, mx0);
        const float nm1 = fmaxf(m1, mx1);
        const float cr0 = ex2(m0 - nm0);
        const float cr1 = ex2(m1 - nm1);
        m0 = nm0; m1 = nm1;

        float ls0 = 0.f, ls1 = 0.f;
#pragma unroll
        for (int nf = 0; nf < 8; nf++) {
            sa[nf][0] = ex2(sa[nf][0] - nm0);
            sa[nf][1] = ex2(sa[nf][1] - nm0);
            sa[nf][2] = ex2(sa[nf][2] - nm1);
            sa[nf][3] = ex2(sa[nf][3] - nm1);
            ls0 += sa[nf][0] + sa[nf][1];
            ls1 += sa[nf][2] + sa[nf][3];
        }
        ls0 += __shfl_xor_sync(0xffffffffu, ls0, 1);
        ls0 += __shfl_xor_sync(0xffffffffu, ls0, 2);
        ls1 += __shfl_xor_sync(0xffffffffu, ls1, 1);
        ls1 += __shfl_xor_sync(0xffffffffu, ls1, 2);
        l0 = l0 * cr0 + ls0;
        l1 = l1 * cr1 + ls1;

#pragma unroll
        for (int df = 0; df < 8; df++) {
            of[df][0] *= cr0; of[df][1] *= cr0;
            of[df][2] *= cr1; of[df][3] *= cr1;
        }

        unsigned pf[4][4];
#pragma unroll
        for (int kc = 0; kc < 4; kc++) {
            pf[kc][0] = packh2(sa[2 * kc][0],     sa[2 * kc][1]);
            pf[kc][1] = packh2(sa[2 * kc][2],     sa[2 * kc][3]);
            pf[kc][2] = packh2(sa[2 * kc + 1][0], sa[2 * kc + 1][1]);
            pf[kc][3] = packh2(sa[2 * kc + 1][2], sa[2 * kc + 1][3]);
        }

        {
            const int vrow = (lane & 7) + ((lane >> 3) & 3) * 8;
#pragma unroll
            for (int df = 0; df < 8; df++) {
                unsigned b0, b1, b2, b3;
                ldsm4t(vb + (unsigned)(vrow * KVSTR + df * 8) * 2u, b0, b1, b2, b3);
                mma16(of[df], pf[0], b0, b1);
                mma16(of[df], pf[1], b2, b3);
                ldsm4t(vb + (unsigned)((vrow + 32) * KVSTR + df * 8) * 2u, b0, b1, b2, b3);
                mma16(of[df], pf[2], b0, b1);
                mma16(of[df], pf[3], b2, b3);
            }
        }
    }

    const int b = bh / NH;
    const int h = bh % NH;
    const float il0 = 1.f / l0;
    const float il1 = 1.f / l1;
#pragma unroll
    for (int df = 0; df < 8; df++) {
        const int col = h * 64 + df * 8 + 2 * t;
        *(__half2*)&g_Y[(size_t)(b * TSEQ + r0) * CDIM + col] =
            __floats2half2_rn(of[df][0] * il0, of[df][1] * il0);
        *(__half2*)&g_Y[(size_t)(b * TSEQ + r1) * CDIM + col] =
            __floats2half2_rn(of[df][2] * il1, of[df][3] * il1);
    }
}

// ---------------------------------------------------------------------------
extern "C" void kernel_launch(void* const* d_in, const int* in_sizes, int n_in,
                              void* d_out, int out_size)
{
    const float* x     = (const float*)d_in[0];
    const float* Wqkv  = (const float*)d_in[1];
    const float* bqkv  = (const float*)d_in[2];
    const float* Wproj = (const float*)d_in[3];
    const float* bproj = (const float*)d_in[4];
    float* out = (float*)d_out;

    cudaFuncSetAttribute(qkv_gemm_f16, cudaFuncAttributeMaxDynamicSharedMemorySize, GEMM_SMEM);
    cudaFuncSetAttribute(proj_gemm_f16, cudaFuncAttributeMaxDynamicSharedMemorySize, GEMM_SMEM);
    cudaFuncSetAttribute(attn_fa16, cudaFuncAttributeMaxDynamicSharedMemorySize, ATT_SMEM);

    f2h_all<<<NTOT / 2048, 256>>>(x, Wqkv, Wproj);
    qkv_gemm_f16<<<dim3(NQKV / 128, MTOK / 128), 256, GEMM_SMEM>>>(bqkv);
    attn_fa16<<<dim3(TSEQ / 128, BH), 256, ATT_SMEM>>>();
    proj_gemm_f16<<<dim3(CDIM / 128, MTOK / 128), 256, GEMM_SMEM>>>(bproj, out);
}

// round 17
// speedup vs baseline: 1.0051x; 1.0020x over previous
#include <cuda_runtime.h>
#include <cuda_fp16.h>
#include <math.h>

#define BSZ 2
#define TSEQ 4096
#define CDIM 768
#define NH 12
#define HD 64
#define MTOK (BSZ * TSEQ)      // 8192
#define NQKV (3 * CDIM)        // 2304
#define BH (BSZ * NH)          // 24

// Scratch (allocation-free rule: device globals) — all fp16
__device__ __half g_Q[(size_t)BH * TSEQ * HD];   // [b*H+h, T, D], pre-scaled
__device__ __half g_K[(size_t)BH * TSEQ * HD];
__device__ __half g_V[(size_t)BH * TSEQ * HD];
__device__ __half g_Y[(size_t)MTOK * CDIM];      // attention out, [B*T, C]
__device__ __half g_Xh[(size_t)MTOK * CDIM];     // x in fp16
__device__ __half g_Wqkvh[(size_t)CDIM * NQKV];  // Wqkv in fp16
__device__ __half g_Wprojh[(size_t)CDIM * CDIM]; // Wproj in fp16

// ---------------------------------------------------------------------------
// helpers
// ---------------------------------------------------------------------------
__device__ __forceinline__ void mma16(float* c, const unsigned* a, unsigned b0, unsigned b1) {
    asm volatile(
        "mma.sync.aligned.m16n8k16.row.col.f32.f16.f16.f32 "
        "{%0,%1,%2,%3}, {%4,%5,%6,%7}, {%8,%9}, {%0,%1,%2,%3};"
        : "+f"(c[0]), "+f"(c[1]), "+f"(c[2]), "+f"(c[3])
        : "r"(a[0]), "r"(a[1]), "r"(a[2]), "r"(a[3]), "r"(b0), "r"(b1));
}
__device__ __forceinline__ void ldsm4(unsigned addr, unsigned& r0, unsigned& r1,
                                      unsigned& r2, unsigned& r3) {
    asm volatile("ldmatrix.sync.aligned.m8n8.x4.shared.b16 {%0,%1,%2,%3}, [%4];"
                 : "=r"(r0), "=r"(r1), "=r"(r2), "=r"(r3) : "r"(addr));
}
__device__ __forceinline__ void ldsm4t(unsigned addr, unsigned& r0, unsigned& r1,
                                       unsigned& r2, unsigned& r3) {
    asm volatile("ldmatrix.sync.aligned.m8n8.x4.trans.shared.b16 {%0,%1,%2,%3}, [%4];"
                 : "=r"(r0), "=r"(r1), "=r"(r2), "=r"(r3) : "r"(addr));
}
__device__ __forceinline__ float ex2(float x) {
    float r;
    asm("ex2.approx.f32 %0, %1;" : "=f"(r) : "f"(x));
    return r;
}
__device__ __forceinline__ unsigned packh2(float a, float b) {
    __half2 h = __floats2half2_rn(a, b);
    return *(unsigned*)&h;
}
__device__ __forceinline__ uint4 cvt8(const float* p) {
    float4 f0 = *(const float4*)p;
    float4 f1 = *(const float4*)(p + 4);
    uint4 u;
    u.x = packh2(f0.x, f0.y); u.y = packh2(f0.z, f0.w);
    u.z = packh2(f1.x, f1.y); u.w = packh2(f1.z, f1.w);
    return u;
}
__device__ __forceinline__ void cpa16(unsigned dst, const void* src) {
    asm volatile("cp.async.cg.shared.global [%0], [%1], 16;" :: "r"(dst), "l"(src));
}
#define CPCOMMIT() asm volatile("cp.async.commit_group;")
#define CPWAIT0()  asm volatile("cp.async.wait_group 0;")
#define CPWAIT1()  asm volatile("cp.async.wait_group 1;")
#define CPWAIT2()  asm volatile("cp.async.wait_group 2;")

#define QS (0.125f * 1.4426950408889634f)   // 1/sqrt(D) * log2(e)

// ---------------------------------------------------------------------------
// Kernel 0: fused fp32 -> fp16 convert for x, Wqkv, Wproj (one launch)
// ---------------------------------------------------------------------------
#define NX (MTOK * CDIM)        // 6291456
#define NW (CDIM * NQKV)        // 1769472
#define NP (CDIM * CDIM)        // 589824
#define NTOT (NX + NW + NP)     // 8650752 (divisible by 8)

__global__ __launch_bounds__(256) void f2h_all(const float* __restrict__ x,
                                               const float* __restrict__ wq,
                                               const float* __restrict__ wp)
{
    const int i = ((int)blockIdx.x * 256 + (int)threadIdx.x) * 8;
    if (i < NX) {
        *(uint4*)(g_Xh + i) = cvt8(x + i);
    } else if (i < NX + NW) {
        const int j = i - NX;
        *(uint4*)(g_Wqkvh + j) = cvt8(wq + j);
    } else if (i < NTOT) {
        const int j = i - NX - NW;
        *(uint4*)(g_Wprojh + j) = cvt8(wp + j);
    }
}

// ---------------------------------------------------------------------------
// GEMM (fp16 mma + ldmatrix + 3-stage cp.async, single sync/iter, 2 CTAs/SM)
// 128x128x64 tile, 256 threads (8 warps, warp tile 64x32).
// ---------------------------------------------------------------------------
#define ASTR 72
#define BSTR 136
#define STAGEH (128 * ASTR + 64 * BSTR)   // halves per stage (17920)
#define NSTAGE 3
#define GEMM_SMEM (NSTAGE * STAGEH * 2)   // 107520 bytes

__device__ __forceinline__ void scatter_qkv2(int m, int n, float v0, float v1) {
    const int b = m >> 12;
    const int tt = m & 4095;
    const int sel = n / CDIM;            // 0=Q,1=K,2=V
    const int r = n - sel * CDIM;
    const int h = r >> 6;
    const int d = r & 63;
    if (sel == 0) { v0 *= QS; v1 *= QS; }
    __half* dst = (sel == 0) ? g_Q : ((sel == 1) ? g_K : g_V);
    *(__half2*)&dst[((size_t)(b * NH + h) * TSEQ + tt) * HD + d] = __floats2half2_rn(v0, v1);
}

template <bool IS_QKV>
__device__ __forceinline__ void gemm_f16_body(const __half* __restrict__ Ag,
                                              const __half* __restrict__ Bg,
                                              const float* __restrict__ bias,
                                              float* __restrict__ out, int ldb)
{
    extern __shared__ __half dsm[];
    const unsigned smb = (unsigned)__cvta_generic_to_shared(dsm);

    const int tid = (int)threadIdx.x;
    const int lane = tid & 31;
    const int wid = tid >> 5;
    const int g = lane >> 2;
    const int t = lane & 3;
    const int m0 = blockIdx.y * 128;
    const int n0 = blockIdx.x * 128;
    const int m0w = (wid & 1) * 64;
    const int n0w = (wid >> 1) * 32;

    float acc[4][4][4];
#pragma unroll
    for (int i = 0; i < 4; i++)
#pragma unroll
        for (int j = 0; j < 4; j++)
#pragma unroll
            for (int k = 0; k < 4; k++) acc[i][j][k] = 0.f;

    const int ar = tid >> 1, ac = (tid & 1) * 32;
    const int br = tid >> 2, bc = (tid & 3) * 32;
    const int arow = lane & 15;
    const int koff = (lane & 16) ? 8 : 0;
    const int trow = (lane & 7) + ((lane >> 3) & 3) * 8;

    const int NIT = CDIM / 64;   // 12

    auto prefetch = [&](int it, int s) {
        const int kb = it * 64;
        const unsigned abase = smb + (unsigned)(s * STAGEH) * 2u;
        const unsigned bbase = abase + (unsigned)(128 * ASTR) * 2u;
        const __half* asrc = Ag + (size_t)(m0 + ar) * CDIM + kb + ac;
        const unsigned adst = abase + (unsigned)(ar * ASTR + ac) * 2u;
#pragma unroll
        for (int v = 0; v < 4; v++) cpa16(adst + v * 16u, asrc + v * 8);
        const __half* bsrc = Bg + (size_t)(kb + br) * ldb + n0 + bc;
        const unsigned bdst = bbase + (unsigned)(br * BSTR + bc) * 2u;
#pragma unroll
        for (int v = 0; v < 4; v++) cpa16(bdst + v * 16u, bsrc + v * 8);
    };

    prefetch(0, 0); CPCOMMIT();
    prefetch(1, 1); CPCOMMIT();

    int s = 0;
    int ps = 2;
    for (int it = 0; it < NIT; it++) {
        CPWAIT1();
        __syncthreads();
        if (it + 2 < NIT) prefetch(it + 2, ps);
        CPCOMMIT();

        const unsigned asb = smb + (unsigned)(s * STAGEH) * 2u;
        const unsigned bsb = asb + (unsigned)(128 * ASTR) * 2u;

#pragma unroll
        for (int kc = 0; kc < 2; kc++) {
            unsigned bb[4][4];
#pragma unroll
            for (int nf = 0; nf < 4; nf++)
                ldsm4t(bsb + (unsigned)((kc * 32 + trow) * BSTR + n0w + nf * 8) * 2u,
                       bb[nf][0], bb[nf][1], bb[nf][2], bb[nf][3]);
#pragma unroll
            for (int mf = 0; mf < 4; mf++) {
                unsigned a0[4], a1[4];
                const unsigned base = asb +
                    (unsigned)((m0w + mf * 16 + arow) * ASTR + kc * 32 + koff) * 2u;
                ldsm4(base,      a0[0], a0[1], a0[2], a0[3]);
                ldsm4(base + 32, a1[0], a1[1], a1[2], a1[3]);
#pragma unroll
                for (int nf = 0; nf < 4; nf++) {
                    mma16(acc[mf][nf], a0, bb[nf][0], bb[nf][1]);
                    mma16(acc[mf][nf], a1, bb[nf][2], bb[nf][3]);
                }
            }
        }
        s = (s == 2) ? 0 : s + 1;
        ps = (ps == 2) ? 0 : ps + 1;
    }

#pragma unroll
    for (int mf = 0; mf < 4; mf++) {
        const int r0 = m0 + m0w + mf * 16 + g;
#pragma unroll
        for (int nf = 0; nf < 4; nf++) {
            const int c0 = n0 + n0w + nf * 8 + 2 * t;
            const float b0 = bias[c0], b1 = bias[c0 + 1];
            if (IS_QKV) {
                scatter_qkv2(r0,     c0, acc[mf][nf][0] + b0, acc[mf][nf][1] + b1);
                scatter_qkv2(r0 + 8, c0, acc[mf][nf][2] + b0, acc[mf][nf][3] + b1);
            } else {
                *(float2*)&out[(size_t)r0 * CDIM + c0] =
                    make_float2(acc[mf][nf][0] + b0, acc[mf][nf][1] + b1);
                *(float2*)&out[(size_t)(r0 + 8) * CDIM + c0] =
                    make_float2(acc[mf][nf][2] + b0, acc[mf][nf][3] + b1);
            }
        }
    }
}

__global__ __launch_bounds__(256, 2) void qkv_gemm_f16(const float* __restrict__ bias)
{
    gemm_f16_body<true>(g_Xh, g_Wqkvh, bias, nullptr, NQKV);
}

__global__ __launch_bounds__(256, 2) void proj_gemm_f16(const float* __restrict__ bias,
                                                        float* __restrict__ out)
{
    gemm_f16_body<false>(g_Y, g_Wprojh, bias, out, CDIM);
}

// ---------------------------------------------------------------------------
// Kernel 2: causal flash attention, fp16 mma, 4-stage cp.async K/V ring,
// single sync per tile. Block = 128 q x 64 kv, 8 warps.  [R9 winner]
// ---------------------------------------------------------------------------
#define KVSTR 72
#define KVBUF (64 * KVSTR)             // halves per K or V buffer (4608)
#define KVSTAGE 4
#define ATT_SMEM (KVSTAGE * 2 * KVBUF * 2)   // 73728 bytes

__global__ __launch_bounds__(256, 2) void attn_fa16()
{
    extern __shared__ __half sm[];
    const unsigned smb = (unsigned)__cvta_generic_to_shared(sm);

    const int qt  = (int)gridDim.x - 1 - (int)blockIdx.x;
    const int bh  = (int)blockIdx.y;
    const int tid = (int)threadIdx.x;
    const int lane = tid & 31;
    const int wid  = tid >> 5;
    const int g = lane >> 2;
    const int t = lane & 3;

    const __half* Qg = g_Q + (size_t)bh * TSEQ * HD + (size_t)qt * 128 * HD;
    const __half* Kg = g_K + (size_t)bh * TSEQ * HD;
    const __half* Vg = g_V + (size_t)bh * TSEQ * HD;

    // ---- stage Q into stage-0 region (consumed before ring starts)
    {
        const int r = tid >> 1;
        const int c0 = (tid & 1) * 32;
        const __half* src = Qg + r * 64 + c0;
        const unsigned dst = smb + (unsigned)(r * KVSTR + c0) * 2u;
#pragma unroll
        for (int v = 0; v < 4; v++) cpa16(dst + v * 16u, src + v * 8);
        CPCOMMIT();
        CPWAIT0();
    }
    __syncthreads();

    unsigned qf[4][4];
    {
        const int qrow = wid * 16 + (lane & 15);
        const int koff = (lane & 16) ? 8 : 0;
#pragma unroll
        for (int ks = 0; ks < 4; ks++)
            ldsm4(smb + (unsigned)(qrow * KVSTR + ks * 16 + koff) * 2u,
                  qf[ks][0], qf[ks][1], qf[ks][2], qf[ks][3]);
    }
    __syncthreads();

    float of[8][4];
#pragma unroll
    for (int i = 0; i < 8; i++)
#pragma unroll
        for (int j = 0; j < 4; j++) of[i][j] = 0.f;
    float m0 = -1e30f, m1 = -1e30f, l0 = 0.f, l1 = 0.f;

    const int r0 = qt * 128 + wid * 16 + g;
    const int r1 = r0 + 8;
    const int ntiles = 2 * qt + 2;

    const int kvr = tid >> 2;
    const int kvc = (tid & 3) * 16;
    auto prefetch_kv = [&](int jt, int s) {
        const unsigned kdst = smb + (unsigned)(s * 2 * KVBUF + kvr * KVSTR + kvc) * 2u;
        const unsigned vdst = kdst + (unsigned)KVBUF * 2u;
        const __half* ks = Kg + (size_t)(jt * 64 + kvr) * 64 + kvc;
        const __half* vs = Vg + (size_t)(jt * 64 + kvr) * 64 + kvc;
        cpa16(kdst,       ks);
        cpa16(kdst + 16u, ks + 8);
        cpa16(vdst,       vs);
        cpa16(vdst + 16u, vs + 8);
    };

    // prologue: 3 tiles in flight (empty commits if fewer tiles)
    prefetch_kv(0, 0); CPCOMMIT();
    if (1 < ntiles) prefetch_kv(1, 1);
    CPCOMMIT();
    if (2 < ntiles) prefetch_kv(2, 2);
    CPCOMMIT();

    for (int jt = 0; jt < ntiles; jt++) {
        CPWAIT2();
        __syncthreads();
        if (jt + 3 < ntiles) prefetch_kv(jt + 3, (jt + 3) & 3);
        CPCOMMIT();

        const int s = jt & 3;
        const unsigned kb = smb + (unsigned)(s * 2 * KVBUF) * 2u;
        const unsigned vb = kb + (unsigned)KVBUF * 2u;

        float sa[8][4];
#pragma unroll
        for (int i = 0; i < 8; i++)
#pragma unroll
            for (int j = 0; j < 4; j++) sa[i][j] = 0.f;

        {
            const int nrow = (lane & 7);
            const int kc = ((lane >> 3) & 3) * 8;
#pragma unroll
            for (int nf = 0; nf < 8; nf++) {
                unsigned b0, b1, b2, b3;
                ldsm4(kb + (unsigned)((nf * 8 + nrow) * KVSTR + kc) * 2u, b0, b1, b2, b3);
                mma16(sa[nf], qf[0], b0, b1);
                mma16(sa[nf], qf[1], b2, b3);
                ldsm4(kb + (unsigned)((nf * 8 + nrow) * KVSTR + 32 + kc) * 2u, b0, b1, b2, b3);
                mma16(sa[nf], qf[2], b0, b1);
                mma16(sa[nf], qf[3], b2, b3);
            }
        }

        if (jt * 64 + 63 > qt * 128 + wid * 16) {
#pragma unroll
            for (int nf = 0; nf < 8; nf++) {
                const int c = jt * 64 + nf * 8 + 2 * t;
                if (c > r0)     sa[nf][0] = -1e30f;
                if (c + 1 > r0) sa[nf][1] = -1e30f;
                if (c > r1)     sa[nf][2] = -1e30f;
                if (c + 1 > r1) sa[nf][3] = -1e30f;
            }
        }

        float mx0 = -1e30f, mx1 = -1e30f;
#pragma unroll
        for (int nf = 0; nf < 8; nf++) {
            mx0 = fmaxf(mx0, fmaxf(sa[nf][0], sa[nf][1]));
            mx1 = fmaxf(mx1, fmaxf(sa[nf][2], sa[nf][3]));
        }
        mx0 = fmaxf(mx0, __shfl_xor_sync(0xffffffffu, mx0, 1));
        mx0 = fmaxf(mx0, __shfl_xor_sync(0xffffffffu, mx0, 2));
        mx1 = fmaxf(mx1, __shfl_xor_sync(0xffffffffu, mx1, 1));
        mx1 = fmaxf(mx1, __shfl_xor_sync(0xffffffffu, mx1, 2));

        const float nm0 = fmaxf(m0, mx0);
        const float nm1 = fmaxf(m1, mx1);
        const float cr0 = ex2(m0 - nm0);
        const float cr1 = ex2(m1 - nm1);
        m0 = nm0; m1 = nm1;

        float ls0 = 0.f, ls1 = 0.f;
#pragma unroll
        for (int nf = 0; nf < 8; nf++) {
            sa[nf][0] = ex2(sa[nf][0] - nm0);
            sa[nf][1] = ex2(sa[nf][1] - nm0);
            sa[nf][2] = ex2(sa[nf][2] - nm1);
            sa[nf][3] = ex2(sa[nf][3] - nm1);
            ls0 += sa[nf][0] + sa[nf][1];
            ls1 += sa[nf][2] + sa[nf][3];
        }
        ls0 += __shfl_xor_sync(0xffffffffu, ls0, 1);
        ls0 += __shfl_xor_sync(0xffffffffu, ls0, 2);
        ls1 += __shfl_xor_sync(0xffffffffu, ls1, 1);
        ls1 += __shfl_xor_sync(0xffffffffu, ls1, 2);
        l0 = l0 * cr0 + ls0;
        l1 = l1 * cr1 + ls1;

#pragma unroll
        for (int df = 0; df < 8; df++) {
            of[df][0] *= cr0; of[df][1] *= cr0;
            of[df][2] *= cr1; of[df][3] *= cr1;
        }

        unsigned pf[4][4];
#pragma unroll
        for (int kc = 0; kc < 4; kc++) {
            pf[kc][0] = packh2(sa[2 * kc][0],     sa[2 * kc][1]);
            pf[kc][1] = packh2(sa[2 * kc][2],     sa[2 * kc][3]);
            pf[kc][2] = packh2(sa[2 * kc + 1][0], sa[2 * kc + 1][1]);
            pf[kc][3] = packh2(sa[2 * kc + 1][2], sa[2 * kc + 1][3]);
        }

        {
            const int vrow = (lane & 7) + ((lane >> 3) & 3) * 8;
#pragma unroll
            for (int df = 0; df < 8; df++) {
                unsigned b0, b1, b2, b3;
                ldsm4t(vb + (unsigned)(vrow * KVSTR + df * 8) * 2u, b0, b1, b2, b3);
                mma16(of[df], pf[0], b0, b1);
                mma16(of[df], pf[1], b2, b3);
                ldsm4t(vb + (unsigned)((vrow + 32) * KVSTR + df * 8) * 2u, b0, b1, b2, b3);
                mma16(of[df], pf[2], b0, b1);
                mma16(of[df], pf[3], b2, b3);
            }
        }
    }

    const int b = bh / NH;
    const int h = bh % NH;
    const float il0 = 1.f / l0;
    const float il1 = 1.f / l1;
#pragma unroll
    for (int df = 0; df < 8; df++) {
        const int col = h * 64 + df * 8 + 2 * t;
        *(__half2*)&g_Y[(size_t)(b * TSEQ + r0) * CDIM + col] =
            __floats2half2_rn(of[df][0] * il0, of[df][1] * il0);
        *(__half2*)&g_Y[(size_t)(b * TSEQ + r1) * CDIM + col] =
            __floats2half2_rn(of[df][2] * il1, of[df][3] * il1);
    }
}

// ---------------------------------------------------------------------------
extern "C" void kernel_launch(void* const* d_in, const int* in_sizes, int n_in,
                              void* d_out, int out_size)
{
    const float* x     = (const float*)d_in[0];
    const float* Wqkv  = (const float*)d_in[1];
    const float* bqkv  = (const float*)d_in[2];
    const float* Wproj = (const float*)d_in[3];
    const float* bproj = (const float*)d_in[4];
    float* out = (float*)d_out;

    cudaFuncSetAttribute(qkv_gemm_f16, cudaFuncAttributeMaxDynamicSharedMemorySize, GEMM_SMEM);
    cudaFuncSetAttribute(proj_gemm_f16, cudaFuncAttributeMaxDynamicSharedMemorySize, GEMM_SMEM);
    cudaFuncSetAttribute(attn_fa16, cudaFuncAttributeMaxDynamicSharedMemorySize, ATT_SMEM);

    f2h_all<<<NTOT / 2048, 256>>>(x, Wqkv, Wproj);
    qkv_gemm_f16<<<dim3(NQKV / 128, MTOK / 128), 256, GEMM_SMEM>>>(bqkv);
    attn_fa16<<<dim3(TSEQ / 128, BH), 256, ATT_SMEM>>>();
    proj_gemm_f16<<<dim3(CDIM / 128, MTOK / 128), 256, GEMM_SMEM>>>(bproj, out);
}